// round 1
// baseline (speedup 1.0000x reference)
#include <cuda_runtime.h>
#include <cuda_bf16.h>

#define BATCH 4
#define SEQL 512
#define TOK (BATCH*SEQL)
#define DM 1536
#define DIP 6448
#define DI 3072
#define CONVD 3328
#define NH 48
#define HD 64
#define DS 128
#define NL 4
#define KC 4
#define FEATD 1552
#define EPSV 1e-5f

// ---------------- workspace (device globals; no allocation allowed) ----------------
__device__ float g_h[TOK*DM];        // hidden state
__device__ float g_x[TOK*DM];        // normed hidden
__device__ float g_zx[TOK*DIP];      // in_proj output
__device__ float g_xBC[TOK*CONVD];   // conv+silu output
__device__ float g_dt[TOK*NH];       // softplus(dt)
__device__ float g_y[TOK*DI];        // scan output / gated-normed
__device__ float g_feat[BATCH*FEATD];

// ---------------- embedding gather ----------------
__global__ void k_embed(const int* __restrict__ ids, const float* __restrict__ emb,
                        float* __restrict__ h) {
    int i = blockIdx.x * blockDim.x + threadIdx.x;
    if (i >= TOK*DM) return;
    int t = i / DM, d = i % DM;
    h[i] = emb[(long)ids[t]*DM + d];
}

// ---------------- rmsnorm over row of length D ----------------
__global__ void k_rmsnorm(const float* __restrict__ in, const float* __restrict__ w,
                          float* __restrict__ out, int D) {
    int row = blockIdx.x;
    const float* x = in + (long)row*D;
    float ss = 0.f;
    for (int d = threadIdx.x; d < D; d += blockDim.x) { float v = x[d]; ss += v*v; }
    __shared__ float red[32];
    for (int o = 16; o; o >>= 1) ss += __shfl_down_sync(0xffffffffu, ss, o);
    if ((threadIdx.x & 31) == 0) red[threadIdx.x >> 5] = ss;
    __syncthreads();
    if (threadIdx.x < 32) {
        float v = (threadIdx.x < (blockDim.x >> 5)) ? red[threadIdx.x] : 0.f;
        for (int o = 16; o; o >>= 1) v += __shfl_down_sync(0xffffffffu, v, o);
        if (threadIdx.x == 0) red[0] = rsqrtf(v / (float)D + EPSV);
    }
    __syncthreads();
    float s = red[0];
    for (int d = threadIdx.x; d < D; d += blockDim.x)
        out[(long)row*D + d] = x[d] * s * w[d];
}

// ---------------- GEMM: C[M,N] = A[M,K] * B[N,K]^T (+C if beta) ----------------
// 128x128 tile, BK=8, 256 threads, 8x8 per thread. M % 128 == 0 assumed; N guarded.
__global__ void k_gemm_nt(const float* __restrict__ A, const float* __restrict__ B,
                          float* __restrict__ C, int M, int N, int K, int beta) {
    __shared__ float sA[8][128];
    __shared__ float sB[8][128];
    int tid = threadIdx.x;
    int m0 = blockIdx.y * 128, n0 = blockIdx.x * 128;
    int lr = tid >> 1;             // 0..127
    int lc = (tid & 1) * 4;        // 0 or 4
    const float* Ap = A + (long)(m0 + lr) * K + lc;
    int brow = n0 + lr;
    bool bvalid = brow < N;
    const float* Bp = B + (long)(bvalid ? brow : 0) * K + lc;

    float acc[8][8];
#pragma unroll
    for (int i = 0; i < 8; i++)
#pragma unroll
        for (int j = 0; j < 8; j++) acc[i][j] = 0.f;

    int ty = tid >> 4, tx = tid & 15;

    for (int k0 = 0; k0 < K; k0 += 8) {
        float4 av = *(const float4*)(Ap + k0);
        float4 bv = bvalid ? *(const float4*)(Bp + k0) : make_float4(0.f,0.f,0.f,0.f);
        sA[lc+0][lr] = av.x; sA[lc+1][lr] = av.y; sA[lc+2][lr] = av.z; sA[lc+3][lr] = av.w;
        sB[lc+0][lr] = bv.x; sB[lc+1][lr] = bv.y; sB[lc+2][lr] = bv.z; sB[lc+3][lr] = bv.w;
        __syncthreads();
#pragma unroll
        for (int k = 0; k < 8; k++) {
            float4 a0 = *(const float4*)&sA[k][ty*8];
            float4 a1 = *(const float4*)&sA[k][ty*8 + 4];
            float4 b0 = *(const float4*)&sB[k][tx*8];
            float4 b1 = *(const float4*)&sB[k][tx*8 + 4];
            float am[8] = {a0.x,a0.y,a0.z,a0.w,a1.x,a1.y,a1.z,a1.w};
            float bn[8] = {b0.x,b0.y,b0.z,b0.w,b1.x,b1.y,b1.z,b1.w};
#pragma unroll
            for (int i = 0; i < 8; i++)
#pragma unroll
                for (int j = 0; j < 8; j++) acc[i][j] += am[i]*bn[j];
        }
        __syncthreads();
    }

#pragma unroll
    for (int i = 0; i < 8; i++) {
        int m = m0 + ty*8 + i;
#pragma unroll
        for (int j = 0; j < 8; j++) {
            int n = n0 + tx*8 + j;
            if (n < N) {
                long idx = (long)m*N + n;
                C[idx] = (beta ? C[idx] : 0.f) + acc[i][j];
            }
        }
    }
}

// ---------------- causal depthwise conv (K=4) + bias + silu ----------------
__global__ void k_conv(const float* __restrict__ zx, const float* __restrict__ w,
                       const float* __restrict__ bconv, float* __restrict__ out) {
    int i = blockIdx.x * blockDim.x + threadIdx.x;
    if (i >= TOK*CONVD) return;
    int c = i % CONVD;
    int t = i / CONVD;
    int s = t % SEQL;
    const float* src = zx + (long)t*DIP + DI + c;
    float acc = bconv[c];
#pragma unroll
    for (int k = 0; k < KC; k++) {
        int ss = s - (KC-1) + k;
        if (ss >= 0) acc += w[c*KC + k] * src[(long)(ss - s) * DIP];
    }
    out[i] = acc / (1.f + expf(-acc));
}

// ---------------- dt = softplus(dt_raw + bias) ----------------
__global__ void k_dt(const float* __restrict__ zx, const float* __restrict__ dtb,
                     float* __restrict__ dt) {
    int i = blockIdx.x * blockDim.x + threadIdx.x;
    if (i >= TOK*NH) return;
    int h = i % NH, t = i / NH;
    float v = zx[(long)t*DIP + DI + CONVD + h] + dtb[h];
    dt[i] = (v > 20.f) ? v : log1pf(expf(v));
}

// ---------------- SSD sequential scan: one CTA per (batch, head) ----------------
__global__ void __launch_bounds__(256, 4) k_scan(
        const float* __restrict__ xBC, const float* __restrict__ dt,
        const float* __restrict__ A_log, const float* __restrict__ Dvec,
        float* __restrict__ y) {
    int b = blockIdx.x / NH;
    int h = blockIdx.x % NH;
    float A = -expf(A_log[h]);
    float Dh = Dvec[h];
    int tid = threadIdx.x;          // 256
    int p = tid >> 2;               // 0..63
    int g = tid & 3;                // 0..3
    int n0 = g * 32;

    float st[32];
#pragma unroll
    for (int j = 0; j < 32; j++) st[j] = 0.f;

    __shared__ float sB[DS], sC[DS], sx[HD];
    __shared__ float sdt;
    const float* base = xBC + (long)b*SEQL*CONVD;

    for (int t = 0; t < SEQL; t++) {
        const float* rowp = base + (long)t*CONVD;
        if (tid < DS)        sB[tid]       = rowp[DI + tid];
        else                 sC[tid - DS]  = rowp[DI + DS + (tid - DS)];
        if (tid >= 192)      sx[tid - 192] = rowp[h*HD + (tid - 192)];
        if (tid == 0)        sdt = dt[((long)b*SEQL + t)*NH + h];
        __syncthreads();
        float dtt = sdt;
        float decay = expf(dtt * A);
        float xv = sx[p];
        float dtx = dtt * xv;
        float acc = 0.f;
#pragma unroll
        for (int j = 0; j < 32; j++) {
            st[j] = st[j]*decay + dtx * sB[n0 + j];
            acc += st[j] * sC[n0 + j];
        }
        acc += __shfl_down_sync(0xffffffffu, acc, 1);
        acc += __shfl_down_sync(0xffffffffu, acc, 2);
        if (g == 0)
            y[((long)b*SEQL + t)*DI + h*HD + p] = acc + Dh * xv;
        __syncthreads();
    }
}

// ---------------- y = rmsnorm(y * silu(z)) * w ----------------
__global__ void k_gatenorm(const float* __restrict__ yin, const float* __restrict__ zx,
                           const float* __restrict__ w, float* __restrict__ out) {
    int row = blockIdx.x;
    const float* yr = yin + (long)row*DI;
    const float* zr = zx + (long)row*DIP;     // z = cols [0, DI)
    __shared__ float sv[DI];
    float ss = 0.f;
    for (int d = threadIdx.x; d < DI; d += blockDim.x) {
        float z = zr[d];
        float v = yr[d] * (z / (1.f + expf(-z)));
        sv[d] = v;
        ss += v*v;
    }
    __shared__ float red[32];
    for (int o = 16; o; o >>= 1) ss += __shfl_down_sync(0xffffffffu, ss, o);
    if ((threadIdx.x & 31) == 0) red[threadIdx.x >> 5] = ss;
    __syncthreads();
    if (threadIdx.x < 32) {
        float v = (threadIdx.x < (blockDim.x >> 5)) ? red[threadIdx.x] : 0.f;
        for (int o = 16; o; o >>= 1) v += __shfl_down_sync(0xffffffffu, v, o);
        if (threadIdx.x == 0) red[0] = rsqrtf(v / (float)DI + EPSV);
    }
    __syncthreads();
    float s = red[0];
    for (int d = threadIdx.x; d < DI; d += blockDim.x)
        out[(long)row*DI + d] = sv[d] * s * w[d];
}

// ---------------- masked mean pool + cat embed concat ----------------
__global__ void k_pool(const float* __restrict__ x, const int* __restrict__ mask,
                       const int* __restrict__ cats, const float* __restrict__ cat_emb,
                       float* __restrict__ feat) {
    int b = blockIdx.x;
    __shared__ float sm[SEQL];
    __shared__ float minv;
    for (int t = threadIdx.x; t < SEQL; t += blockDim.x)
        sm[t] = (float)mask[b*SEQL + t];
    __syncthreads();
    if (threadIdx.x == 0) {
        float s = 0.f;
        for (int t = 0; t < SEQL; t++) s += sm[t];
        if (s < 1e-9f) s = 1e-9f;
        minv = 1.f / s;
    }
    __syncthreads();
    for (int d = threadIdx.x; d < DM; d += blockDim.x) {
        float acc = 0.f;
        for (int t = 0; t < SEQL; t++)
            acc += sm[t] * x[((long)b*SEQL + t)*DM + d];
        feat[b*FEATD + d] = acc * minv;
    }
    if (threadIdx.x < 16)
        feat[b*FEATD + DM + threadIdx.x] = cat_emb[cats[b]*16 + threadIdx.x];
}

// ---------------- classifier heads ----------------
__global__ void k_heads(const float* __restrict__ feat,
                        const float* __restrict__ qw, const float* __restrict__ qb,
                        const float* __restrict__ aw, const float* __restrict__ ab,
                        float* __restrict__ out) {
    int b = blockIdx.y, j = blockIdx.x;   // j in 0..29
    const float* w;
    float bias;
    if (j < 21) { w = qw + j*FEATD; bias = qb[j]; }
    else        { w = aw + (j-21)*FEATD; bias = ab[j-21]; }
    float s = 0.f;
    for (int d = threadIdx.x; d < FEATD; d += blockDim.x)
        s += feat[b*FEATD + d] * w[d];
    __shared__ float red[8];
    for (int o = 16; o; o >>= 1) s += __shfl_down_sync(0xffffffffu, s, o);
    if ((threadIdx.x & 31) == 0) red[threadIdx.x >> 5] = s;
    __syncthreads();
    if (threadIdx.x == 0) {
        float v = 0.f;
        for (int i = 0; i < (int)(blockDim.x >> 5); i++) v += red[i];
        out[b*30 + j] = v + bias;
    }
}

// ---------------- host orchestration ----------------
extern "C" void kernel_launch(void* const* d_in, const int* in_sizes, int n_in,
                              void* d_out, int out_size) {
    const int*   ids      = (const int*)d_in[0];
    const int*   mask     = (const int*)d_in[1];
    const int*   cats     = (const int*)d_in[2];
    const float* emb      = (const float*)d_in[3];
    const float* norm_w   = (const float*)d_in[4];   // [NL, DM]
    const float* in_proj  = (const float*)d_in[5];   // [NL, DIP, DM]
    const float* conv_w   = (const float*)d_in[6];   // [NL, CONVD, KC]
    const float* conv_b   = (const float*)d_in[7];   // [NL, CONVD]
    const float* dt_bias  = (const float*)d_in[8];   // [NL, NH]
    const float* A_log    = (const float*)d_in[9];   // [NL, NH]
    const float* Dvec     = (const float*)d_in[10];  // [NL, NH]
    const float* gnorm_w  = (const float*)d_in[11];  // [NL, DI]
    const float* out_proj = (const float*)d_in[12];  // [NL, DM, DI]
    const float* final_w  = (const float*)d_in[13];
    const float* cat_emb  = (const float*)d_in[14];
    const float* qw       = (const float*)d_in[15];
    const float* qb       = (const float*)d_in[16];
    const float* aw       = (const float*)d_in[17];
    const float* ab       = (const float*)d_in[18];
    float* out = (float*)d_out;

    float *p_h, *p_x, *p_zx, *p_xBC, *p_dt, *p_y, *p_feat;
    cudaGetSymbolAddress((void**)&p_h,    g_h);
    cudaGetSymbolAddress((void**)&p_x,    g_x);
    cudaGetSymbolAddress((void**)&p_zx,   g_zx);
    cudaGetSymbolAddress((void**)&p_xBC,  g_xBC);
    cudaGetSymbolAddress((void**)&p_dt,   g_dt);
    cudaGetSymbolAddress((void**)&p_y,    g_y);
    cudaGetSymbolAddress((void**)&p_feat, g_feat);

    // embedding
    {
        int n = TOK*DM;
        k_embed<<<(n + 255)/256, 256>>>(ids, emb, p_h);
    }

    for (int l = 0; l < NL; l++) {
        // 1. pre-norm
        k_rmsnorm<<<TOK, 256>>>(p_h, norm_w + l*DM, p_x, DM);
        // 2. in_proj GEMM: [TOK, DIP] = x @ W^T
        {
            dim3 grid((DIP + 127)/128, TOK/128);
            k_gemm_nt<<<grid, 256>>>(p_x, in_proj + (long)l*DIP*DM, p_zx,
                                     TOK, DIP, DM, 0);
        }
        // 3. conv + silu
        {
            int n = TOK*CONVD;
            k_conv<<<(n + 255)/256, 256>>>(p_zx, conv_w + (long)l*CONVD*KC,
                                           conv_b + l*CONVD, p_xBC);
        }
        // 4. dt
        {
            int n = TOK*NH;
            k_dt<<<(n + 255)/256, 256>>>(p_zx, dt_bias + l*NH, p_dt);
        }
        // 5. SSD scan
        k_scan<<<BATCH*NH, 256>>>(p_xBC, p_dt, A_log + l*NH, Dvec + l*NH, p_y);
        // 6. gate + group norm
        k_gatenorm<<<TOK, 256>>>(p_y, p_zx, gnorm_w + (long)l*DI, p_y);
        // 7. out_proj GEMM with residual add: h += y @ W^T
        {
            dim3 grid(DM/128, TOK/128);
            k_gemm_nt<<<grid, 256>>>(p_y, out_proj + (long)l*DM*DI, p_h,
                                     TOK, DM, DI, 1);
        }
    }

    // final norm, pool, heads
    k_rmsnorm<<<TOK, 256>>>(p_h, final_w, p_x, DM);
    k_pool<<<BATCH, 256>>>(p_x, mask, cats, cat_emb, p_feat);
    {
        dim3 grid(30, BATCH);
        k_heads<<<grid, 128>>>(p_feat, qw, qb, aw, ab, out);
    }
}

// round 3
// speedup vs baseline: 1.6239x; 1.6239x over previous
#include <cuda_runtime.h>
#include <cuda_bf16.h>
#include <cstdint>

#define BATCH 4
#define SEQL 512
#define TOK (BATCH*SEQL)
#define DM 1536
#define DIP 6448
#define DI 3072
#define CONVD 3328
#define NH 48
#define HD 64
#define DS 128
#define NL 4
#define KC 4
#define FEATD 1552
#define EPSV 1e-5f

// ---------------- workspace (device globals; no allocation allowed) ----------------
__device__ float g_h[TOK*DM];
__device__ float g_x[TOK*DM];
__device__ float g_zx[TOK*DIP];
__device__ float g_xBC[TOK*CONVD];
__device__ float g_dt[TOK*NH];
__device__ float g_y[TOK*DI];
__device__ float g_feat[BATCH*FEATD];

// ================= warp-MMA helpers (arch-portable HMMA) =================
__device__ __forceinline__ uint32_t smem_u32(const void* p) {
    uint32_t a;
    asm("{ .reg .u64 t; cvta.to.shared.u64 t, %1; cvt.u32.u64 %0, t; }" : "=r"(a) : "l"(p));
    return a;
}
__device__ __forceinline__ void ldm4(uint32_t* r, uint32_t addr) {
    asm volatile("ldmatrix.sync.aligned.m8n8.x4.shared.b16 {%0,%1,%2,%3}, [%4];"
                 : "=r"(r[0]), "=r"(r[1]), "=r"(r[2]), "=r"(r[3]) : "r"(addr));
}
__device__ __forceinline__ void mma16816(float* c, const uint32_t* a, uint32_t b0, uint32_t b1) {
    asm volatile("mma.sync.aligned.m16n8k16.row.col.f32.bf16.bf16.f32 "
                 "{%0,%1,%2,%3}, {%4,%5,%6,%7}, {%8,%9}, {%0,%1,%2,%3};"
                 : "+f"(c[0]), "+f"(c[1]), "+f"(c[2]), "+f"(c[3])
                 : "r"(a[0]), "r"(a[1]), "r"(a[2]), "r"(a[3]), "r"(b0), "r"(b1));
}

// split fp32 -> bf16 hi + bf16 lo, stored as 8B each for 4 elements
__device__ __forceinline__ void split_store(char* hi, char* lo, float4 v) {
    __nv_bfloat162 h0 = __floats2bfloat162_rn(v.x, v.y);
    __nv_bfloat162 h1 = __floats2bfloat162_rn(v.z, v.w);
    float2 f0 = __bfloat1622float2(h0);
    float2 f1 = __bfloat1622float2(h1);
    __nv_bfloat162 l0 = __floats2bfloat162_rn(v.x - f0.x, v.y - f0.y);
    __nv_bfloat162 l1 = __floats2bfloat162_rn(v.z - f1.x, v.w - f1.y);
    uint2 uh, ul;
    uh.x = *(uint32_t*)&h0; uh.y = *(uint32_t*)&h1;
    ul.x = *(uint32_t*)&l0; ul.y = *(uint32_t*)&l1;
    *(uint2*)hi = uh;
    *(uint2*)lo = ul;
}

// ============ split-bf16 tensor-core GEMM: C[M,N] = A[M,K] @ B[N,K]^T (+C if beta) ============
// CTA tile 128x128, BK=64, 8 warps of 64x32, 3-pass split bf16.
#define STRB 144                      // smem row stride bytes (64 bf16 + 8 pad)
#define T_AHI 0
#define T_ALO (128*STRB)
#define T_BHI (2*128*STRB)
#define T_BLO (3*128*STRB)
#define GEMM_SMEM (4*128*STRB)

__global__ void __launch_bounds__(256, 2) k_gemm_mma(
        const float* __restrict__ A, const float* __restrict__ B,
        float* __restrict__ C, int N, int K, int beta) {
    extern __shared__ __align__(16) char smem[];
    int tid = threadIdx.x;
    int wid = tid >> 5, lane = tid & 31;
    int m0 = blockIdx.x * 128;
    int n0 = blockIdx.y * 128;
    int wm = wid & 1;          // 0..1 (64 rows each)
    int wn = wid >> 1;         // 0..3 (32 cols each)

    float acc[4][4][4];
#pragma unroll
    for (int i = 0; i < 4; i++)
#pragma unroll
        for (int j = 0; j < 4; j++)
#pragma unroll
            for (int q = 0; q < 4; q++) acc[i][j][q] = 0.f;

    uint32_t sb = smem_u32(smem);
    // ldmatrix per-lane base addresses
    uint32_t aoff = (uint32_t)((wm*64 + (lane & 15)) * STRB + (lane >> 4) * 16);
    uint32_t adrAhi = sb + T_AHI + aoff;
    uint32_t adrAlo = sb + T_ALO + aoff;
    uint32_t boff = (uint32_t)((wn*32 + (lane & 7) + ((lane >> 4) & 1) * 8) * STRB
                               + ((lane >> 3) & 1) * 16);
    uint32_t adrBhi = sb + T_BHI + boff;
    uint32_t adrBlo = sb + T_BLO + boff;

    const int NK = K >> 6;
    for (int kc = 0; kc < NK; kc++) {
        int k0 = kc << 6;
        // ---- load fp32, split to bf16 hi/lo in smem ----
#pragma unroll
        for (int i = 0; i < 8; i++) {
            int idx = (i << 8) + tid;     // 0..2047
            int r = idx >> 4;             // row 0..127
            int c4 = idx & 15;            // float4 group within 64 cols
            int soff = r * STRB + c4 * 8;
            float4 av = *(const float4*)&A[(size_t)(m0 + r) * K + k0 + (c4 << 2)];
            split_store(smem + T_AHI + soff, smem + T_ALO + soff, av);
            int bn = n0 + r;
            float4 bv = (bn < N) ? *(const float4*)&B[(size_t)bn * K + k0 + (c4 << 2)]
                                 : make_float4(0.f, 0.f, 0.f, 0.f);
            split_store(smem + T_BHI + soff, smem + T_BLO + soff, bv);
        }
        __syncthreads();
        // ---- 3-pass MMA over 4 k-steps of 16 ----
#pragma unroll
        for (int kk = 0; kk < 4; kk++) {
            uint32_t kb = kk * 32;
            uint32_t fa[4][4], fb[2][4], fbl[2][4];
#pragma unroll
            for (int mt = 0; mt < 4; mt++) ldm4(fa[mt], adrAhi + mt*16*STRB + kb);
#pragma unroll
            for (int bt = 0; bt < 2; bt++) ldm4(fb[bt], adrBhi + bt*16*STRB + kb);
            // hi * hi
#pragma unroll
            for (int mt = 0; mt < 4; mt++)
#pragma unroll
                for (int nt = 0; nt < 4; nt++)
                    mma16816(acc[mt][nt], fa[mt], fb[nt>>1][(nt&1)*2], fb[nt>>1][(nt&1)*2+1]);
            // hi * lo
#pragma unroll
            for (int bt = 0; bt < 2; bt++) ldm4(fbl[bt], adrBlo + bt*16*STRB + kb);
#pragma unroll
            for (int mt = 0; mt < 4; mt++)
#pragma unroll
                for (int nt = 0; nt < 4; nt++)
                    mma16816(acc[mt][nt], fa[mt], fbl[nt>>1][(nt&1)*2], fbl[nt>>1][(nt&1)*2+1]);
            // lo * hi
#pragma unroll
            for (int mt = 0; mt < 4; mt++) ldm4(fa[mt], adrAlo + mt*16*STRB + kb);
#pragma unroll
            for (int mt = 0; mt < 4; mt++)
#pragma unroll
                for (int nt = 0; nt < 4; nt++)
                    mma16816(acc[mt][nt], fa[mt], fb[nt>>1][(nt&1)*2], fb[nt>>1][(nt&1)*2+1]);
        }
        __syncthreads();
    }

    // ---- epilogue ----
    int mbase = m0 + wm*64 + (lane >> 2);
    int nbase = n0 + wn*32 + (lane & 3)*2;
#pragma unroll
    for (int mt = 0; mt < 4; mt++) {
#pragma unroll
        for (int nt = 0; nt < 4; nt++) {
            int n = nbase + nt*8;
            if (n < N) {
                int m = mbase + mt*16;
                float2 v0 = make_float2(acc[mt][nt][0], acc[mt][nt][1]);
                float2 v1 = make_float2(acc[mt][nt][2], acc[mt][nt][3]);
                float* p0 = &C[(size_t)m * N + n];
                float* p1 = &C[(size_t)(m + 8) * N + n];
                if (beta) {
                    float2 o0 = *(float2*)p0, o1 = *(float2*)p1;
                    v0.x += o0.x; v0.y += o0.y; v1.x += o1.x; v1.y += o1.y;
                }
                *(float2*)p0 = v0;
                *(float2*)p1 = v1;
            }
        }
    }
}

// ---------------- embedding gather ----------------
__global__ void k_embed(const int* __restrict__ ids, const float* __restrict__ emb,
                        float* __restrict__ h) {
    int i = blockIdx.x * blockDim.x + threadIdx.x;
    if (i >= TOK*DM) return;
    int t = i / DM, d = i % DM;
    h[i] = emb[(long)ids[t]*DM + d];
}

// ---------------- rmsnorm ----------------
__global__ void k_rmsnorm(const float* __restrict__ in, const float* __restrict__ w,
                          float* __restrict__ out, int D) {
    int row = blockIdx.x;
    const float* x = in + (long)row*D;
    float ss = 0.f;
    for (int d = threadIdx.x; d < D; d += blockDim.x) { float v = x[d]; ss += v*v; }
    __shared__ float red[32];
    for (int o = 16; o; o >>= 1) ss += __shfl_down_sync(0xffffffffu, ss, o);
    if ((threadIdx.x & 31) == 0) red[threadIdx.x >> 5] = ss;
    __syncthreads();
    if (threadIdx.x < 32) {
        float v = (threadIdx.x < (blockDim.x >> 5)) ? red[threadIdx.x] : 0.f;
        for (int o = 16; o; o >>= 1) v += __shfl_down_sync(0xffffffffu, v, o);
        if (threadIdx.x == 0) red[0] = rsqrtf(v / (float)D + EPSV);
    }
    __syncthreads();
    float s = red[0];
    for (int d = threadIdx.x; d < D; d += blockDim.x)
        out[(long)row*D + d] = x[d] * s * w[d];
}

// ---------------- causal depthwise conv (K=4) + bias + silu ----------------
__global__ void k_conv(const float* __restrict__ zx, const float* __restrict__ w,
                       const float* __restrict__ bconv, float* __restrict__ out) {
    int i = blockIdx.x * blockDim.x + threadIdx.x;
    if (i >= TOK*CONVD) return;
    int c = i % CONVD;
    int t = i / CONVD;
    int s = t % SEQL;
    const float* src = zx + (long)t*DIP + DI + c;
    float acc = bconv[c];
#pragma unroll
    for (int k = 0; k < KC; k++) {
        int ss = s - (KC-1) + k;
        if (ss >= 0) acc += w[c*KC + k] * src[(long)(ss - s) * DIP];
    }
    out[i] = acc / (1.f + expf(-acc));
}

// ---------------- dt = softplus(dt_raw + bias) ----------------
__global__ void k_dt(const float* __restrict__ zx, const float* __restrict__ dtb,
                     float* __restrict__ dt) {
    int i = blockIdx.x * blockDim.x + threadIdx.x;
    if (i >= TOK*NH) return;
    int h = i % NH, t = i / NH;
    float v = zx[(long)t*DIP + DI + CONVD + h] + dtb[h];
    dt[i] = (v > 20.f) ? v : log1pf(expf(v));
}

// ---------------- SSD sequential scan: one CTA per (batch, head) ----------------
__global__ void __launch_bounds__(256, 4) k_scan(
        const float* __restrict__ xBC, const float* __restrict__ dt,
        const float* __restrict__ A_log, const float* __restrict__ Dvec,
        float* __restrict__ y) {
    int b = blockIdx.x / NH;
    int h = blockIdx.x % NH;
    float A = -expf(A_log[h]);
    float Dh = Dvec[h];
    int tid = threadIdx.x;
    int p = tid >> 2;
    int g = tid & 3;
    int n0 = g * 32;

    float st[32];
#pragma unroll
    for (int j = 0; j < 32; j++) st[j] = 0.f;

    __shared__ float sB[DS], sC[DS], sx[HD];
    __shared__ float sdt;
    const float* base = xBC + (long)b*SEQL*CONVD;

    for (int t = 0; t < SEQL; t++) {
        const float* rowp = base + (long)t*CONVD;
        if (tid < DS)        sB[tid]       = rowp[DI + tid];
        else                 sC[tid - DS]  = rowp[DI + DS + (tid - DS)];
        if (tid >= 192)      sx[tid - 192] = rowp[h*HD + (tid - 192)];
        if (tid == 0)        sdt = dt[((long)b*SEQL + t)*NH + h];
        __syncthreads();
        float dtt = sdt;
        float decay = expf(dtt * A);
        float xv = sx[p];
        float dtx = dtt * xv;
        float acc = 0.f;
#pragma unroll
        for (int j = 0; j < 32; j++) {
            st[j] = st[j]*decay + dtx * sB[n0 + j];
            acc += st[j] * sC[n0 + j];
        }
        acc += __shfl_down_sync(0xffffffffu, acc, 1);
        acc += __shfl_down_sync(0xffffffffu, acc, 2);
        if (g == 0)
            y[((long)b*SEQL + t)*DI + h*HD + p] = acc + Dh * xv;
        __syncthreads();
    }
}

// ---------------- y = rmsnorm(y * silu(z)) * w ----------------
__global__ void k_gatenorm(const float* __restrict__ yin, const float* __restrict__ zx,
                           const float* __restrict__ w, float* __restrict__ out) {
    int row = blockIdx.x;
    const float* yr = yin + (long)row*DI;
    const float* zr = zx + (long)row*DIP;
    __shared__ float sv[DI];
    float ss = 0.f;
    for (int d = threadIdx.x; d < DI; d += blockDim.x) {
        float z = zr[d];
        float v = yr[d] * (z / (1.f + expf(-z)));
        sv[d] = v;
        ss += v*v;
    }
    __shared__ float red[32];
    for (int o = 16; o; o >>= 1) ss += __shfl_down_sync(0xffffffffu, ss, o);
    if ((threadIdx.x & 31) == 0) red[threadIdx.x >> 5] = ss;
    __syncthreads();
    if (threadIdx.x < 32) {
        float v = (threadIdx.x < (blockDim.x >> 5)) ? red[threadIdx.x] : 0.f;
        for (int o = 16; o; o >>= 1) v += __shfl_down_sync(0xffffffffu, v, o);
        if (threadIdx.x == 0) red[0] = rsqrtf(v / (float)DI + EPSV);
    }
    __syncthreads();
    float s = red[0];
    for (int d = threadIdx.x; d < DI; d += blockDim.x)
        out[(long)row*DI + d] = sv[d] * s * w[d];
}

// ---------------- masked mean pool + cat embed concat ----------------
__global__ void k_pool(const float* __restrict__ x, const int* __restrict__ mask,
                       const int* __restrict__ cats, const float* __restrict__ cat_emb,
                       float* __restrict__ feat) {
    int b = blockIdx.x;
    __shared__ float sm[SEQL];
    __shared__ float minv;
    for (int t = threadIdx.x; t < SEQL; t += blockDim.x)
        sm[t] = (float)mask[b*SEQL + t];
    __syncthreads();
    if (threadIdx.x == 0) {
        float s = 0.f;
        for (int t = 0; t < SEQL; t++) s += sm[t];
        if (s < 1e-9f) s = 1e-9f;
        minv = 1.f / s;
    }
    __syncthreads();
    for (int d = threadIdx.x; d < DM; d += blockDim.x) {
        float acc = 0.f;
        for (int t = 0; t < SEQL; t++)
            acc += sm[t] * x[((long)b*SEQL + t)*DM + d];
        feat[b*FEATD + d] = acc * minv;
    }
    if (threadIdx.x < 16)
        feat[b*FEATD + DM + threadIdx.x] = cat_emb[cats[b]*16 + threadIdx.x];
}

// ---------------- classifier heads ----------------
__global__ void k_heads(const float* __restrict__ feat,
                        const float* __restrict__ qw, const float* __restrict__ qb,
                        const float* __restrict__ aw, const float* __restrict__ ab,
                        float* __restrict__ out) {
    int b = blockIdx.y, j = blockIdx.x;
    const float* w;
    float bias;
    if (j < 21) { w = qw + j*FEATD; bias = qb[j]; }
    else        { w = aw + (j-21)*FEATD; bias = ab[j-21]; }
    float s = 0.f;
    for (int d = threadIdx.x; d < FEATD; d += blockDim.x)
        s += feat[b*FEATD + d] * w[d];
    __shared__ float red[8];
    for (int o = 16; o; o >>= 1) s += __shfl_down_sync(0xffffffffu, s, o);
    if ((threadIdx.x & 31) == 0) red[threadIdx.x >> 5] = s;
    __syncthreads();
    if (threadIdx.x == 0) {
        float v = 0.f;
        for (int i = 0; i < (int)(blockDim.x >> 5); i++) v += red[i];
        out[b*30 + j] = v + bias;
    }
}

// ---------------- host orchestration ----------------
extern "C" void kernel_launch(void* const* d_in, const int* in_sizes, int n_in,
                              void* d_out, int out_size) {
    const int*   ids      = (const int*)d_in[0];
    const int*   mask     = (const int*)d_in[1];
    const int*   cats     = (const int*)d_in[2];
    const float* emb      = (const float*)d_in[3];
    const float* norm_w   = (const float*)d_in[4];
    const float* in_proj  = (const float*)d_in[5];
    const float* conv_w   = (const float*)d_in[6];
    const float* conv_b   = (const float*)d_in[7];
    const float* dt_bias  = (const float*)d_in[8];
    const float* A_log    = (const float*)d_in[9];
    const float* Dvec     = (const float*)d_in[10];
    const float* gnorm_w  = (const float*)d_in[11];
    const float* out_proj = (const float*)d_in[12];
    const float* final_w  = (const float*)d_in[13];
    const float* cat_emb  = (const float*)d_in[14];
    const float* qw       = (const float*)d_in[15];
    const float* qb       = (const float*)d_in[16];
    const float* aw       = (const float*)d_in[17];
    const float* ab       = (const float*)d_in[18];
    float* out = (float*)d_out;

    float *p_h, *p_x, *p_zx, *p_xBC, *p_dt, *p_y, *p_feat;
    cudaGetSymbolAddress((void**)&p_h,    g_h);
    cudaGetSymbolAddress((void**)&p_x,    g_x);
    cudaGetSymbolAddress((void**)&p_zx,   g_zx);
    cudaGetSymbolAddress((void**)&p_xBC,  g_xBC);
    cudaGetSymbolAddress((void**)&p_dt,   g_dt);
    cudaGetSymbolAddress((void**)&p_y,    g_y);
    cudaGetSymbolAddress((void**)&p_feat, g_feat);

    cudaFuncSetAttribute(k_gemm_mma, cudaFuncAttributeMaxDynamicSharedMemorySize, GEMM_SMEM);

    {
        int n = TOK*DM;
        k_embed<<<(n + 255)/256, 256>>>(ids, emb, p_h);
    }

    for (int l = 0; l < NL; l++) {
        k_rmsnorm<<<TOK, 256>>>(p_h, norm_w + l*DM, p_x, DM);
        {
            dim3 grid(TOK/128, (DIP + 127)/128);
            k_gemm_mma<<<grid, 256, GEMM_SMEM>>>(p_x, in_proj + (long)l*DIP*DM, p_zx,
                                                 DIP, DM, 0);
        }
        {
            int n = TOK*CONVD;
            k_conv<<<(n + 255)/256, 256>>>(p_zx, conv_w + (long)l*CONVD*KC,
                                           conv_b + l*CONVD, p_xBC);
        }
        {
            int n = TOK*NH;
            k_dt<<<(n + 255)/256, 256>>>(p_zx, dt_bias + l*NH, p_dt);
        }
        k_scan<<<BATCH*NH, 256>>>(p_xBC, p_dt, A_log + l*NH, Dvec + l*NH, p_y);
        k_gatenorm<<<TOK, 256>>>(p_y, p_zx, gnorm_w + (long)l*DI, p_y);
        {
            dim3 grid(TOK/128, DM/128);
            k_gemm_mma<<<grid, 256, GEMM_SMEM>>>(p_y, out_proj + (long)l*DM*DI, p_h,
                                                 DM, DI, 1);
        }
    }

    k_rmsnorm<<<TOK, 256>>>(p_h, final_w, p_x, DM);
    k_pool<<<BATCH, 256>>>(p_x, mask, cats, cat_emb, p_feat);
    {
        dim3 grid(30, BATCH);
        k_heads<<<grid, 128>>>(p_feat, qw, qb, aw, ab, out);
    }
}